// round 7
// baseline (speedup 1.0000x reference)
#include <cuda_runtime.h>
#include <math.h>

#define NB 16
#define NC 256
#define PLANE 3136
#define NPLANES 4096
typedef unsigned long long ull;

// scratch (static device globals; no allocation)
__device__ float g_xfuse[NPLANES * PLANE];   // 51.4 MB
__device__ float g_pooled[NB * 49 * NC];     // [B][pos][C]
__device__ float g_h[NB * 50 * 64];          // hidden layer (pos 49 = mean)
__device__ float g_wdyn[NB * 49 * NC];       // [B][pos][C]
__device__ float g_bdyn[NB * NC];            // [B][C]
__device__ float g_pw1T[256 * 64];           // [k][o]
__device__ float g_pw2T[64 * 1024];          // [k][oc]
__device__ float g_w1T[49 * 1024];           // [pos][g*C+c]

__device__ __forceinline__ void ffma2(ull& d, ull a, ull b) {
    asm("fma.rn.f32x2 %0, %1, %2, %0;" : "+l"(d) : "l"(a), "l"(b));
}
__device__ __forceinline__ float2 u2f2(ull v) {
    float2 r;
    r.x = __uint_as_float((unsigned)v);
    r.y = __uint_as_float((unsigned)(v >> 32));
    return r;
}

// ---------------------------------------------------------------------------
// Kernel 1: fused dw3x3+BN (x2), relu6 gate, x_fuse, 7x7 block-mean pool.
// Blocks >= NPLANES instead perform the small weight transposes.
// (R4 form: LDS.64 row reads + po register-pair recombine.)
// ---------------------------------------------------------------------------
__global__ __launch_bounds__(448, 3) void k_fuse(
    const float* __restrict__ x1,
    const float* __restrict__ dw1_w, const float* __restrict__ dw1_g,
    const float* __restrict__ dw1_b, const float* __restrict__ dw1_m,
    const float* __restrict__ dw1_v,
    const float* __restrict__ dw2_w, const float* __restrict__ dw2_g,
    const float* __restrict__ dw2_b, const float* __restrict__ dw2_m,
    const float* __restrict__ dw2_v,
    const float* __restrict__ pw1, const float* __restrict__ pw2,
    const float* __restrict__ w1grp) {
    const int tid = threadIdx.x;

    if (blockIdx.x >= NPLANES) {           // transpose side-work
        int i = (blockIdx.x - NPLANES) * 448 + tid;
        if (i < 16384) {                   // pw1 [64,256] -> [256,64]
            int k = i >> 6, o = i & 63;
            g_pw1T[i] = pw1[o * 256 + k];
        } else if (i < 81920) {            // pw2 [1024,64] -> [64,1024]
            int j = i - 16384;
            int k = j >> 10, oc = j & 1023;
            g_pw2T[j] = pw2[oc * 64 + k];
        } else if (i < 132096) {           // weight1 [G*C,49] -> [49,G*C]
            int l = i - 81920;
            int pos = l / 1024, gc = l & 1023;
            g_w1T[l] = w1grp[gc * 49 + pos];
        }
        return;
    }

    __shared__ float s[58 * 60];           // tile, halo 1, stride 60
    __shared__ float2 sw1[9], sw2[9];      // packed (w,w) weights
    __shared__ float partial[392];

    const int blk = blockIdx.x;
    const int b = blk >> 8, c = blk & 255;

    // halo zeroing (rows 0,57 x 0..57; rows 1..56 x in {0,57}); interior f4
    if (tid < 228) {
        if (tid < 116) {
            int r = (tid < 58) ? 0 : 57;
            int x = (tid < 58) ? tid : tid - 58;
            s[r * 60 + x] = 0.f;
        } else {
            int j = tid - 116;
            int r = 1 + (j >> 1);
            int x = (j & 1) ? 57 : 0;
            s[r * 60 + x] = 0.f;
        }
    }
    {
        const float4* __restrict__ xp4 =
            (const float4*)(x1 + (size_t)blk * PLANE);
        for (int idx = tid; idx < 784; idx += 448) {
            int r = idx / 14, c4 = idx - r * 14;
            float4 v = xp4[idx];
            float* d = &s[(r + 1) * 60 + 1 + c4 * 4];
            d[0] = v.x; d[1] = v.y; d[2] = v.z; d[3] = v.w;
        }
    }
    // BN-folded channel scalars
    const float s1 = dw1_g[c] * rsqrtf(dw1_v[c] + 1e-5f);
    const float s2 = dw2_g[c] * rsqrtf(dw2_v[c] + 1e-5f);
    const float bb1 = dw1_b[c] - dw1_m[c] * s1;
    const float bb2 = dw2_b[c] - dw2_m[c] * s2;
    if (tid < 9) {
        float wa = dw1_w[c * 9 + tid] * s1;
        float wb = dw2_w[c * 9 + tid] * s2;
        sw1[tid] = make_float2(wa, wa);
        sw2[tid] = make_float2(wb, wb);
    }
    __syncthreads();

    if (tid < 392) {
        const int row = tid / 7;
        const int cg = tid - row * 7;
        ull aA[4] = {0, 0, 0, 0}, aB[4] = {0, 0, 0, 0};
#pragma unroll
        for (int ky = 0; ky < 3; ky++) {
            const float* rp = &s[(row + ky) * 60 + cg * 8];
            ull pe[5];
#pragma unroll
            for (int k = 0; k < 5; k++) pe[k] = *(const ull*)(rp + 2 * k);
            ull po[4];
#pragma unroll
            for (int m = 0; m < 4; m++)
                po[m] = (pe[m] >> 32) | (pe[m + 1] << 32);
#pragma unroll
            for (int t = 0; t < 2; t++) {   // kx = 0, 2
                ull wa = *(const ull*)&sw1[ky * 3 + 2 * t];
                ull wb = *(const ull*)&sw2[ky * 3 + 2 * t];
#pragma unroll
                for (int j = 0; j < 4; j++) {
                    ffma2(aA[j], wa, pe[j + t]);
                    ffma2(aB[j], wb, pe[j + t]);
                }
            }
            {                               // kx = 1
                ull wa = *(const ull*)&sw1[ky * 3 + 1];
                ull wb = *(const ull*)&sw2[ky * 3 + 1];
#pragma unroll
                for (int j = 0; j < 4; j++) {
                    ffma2(aA[j], wa, po[j]);
                    ffma2(aB[j], wb, po[j]);
                }
            }
        }
        float f[8];
        float rsum = 0.f;
#pragma unroll
        for (int j = 0; j < 4; j++) {
            float2 pa = u2f2(aA[j]), pb = u2f2(aB[j]);
            float a0 = fminf(fmaxf(pa.x + bb1, 0.f), 6.f);
            float a1 = fminf(fmaxf(pa.y + bb1, 0.f), 6.f);
            float v0 = a0 * (pb.x + bb2);
            float v1 = a1 * (pb.y + bb2);
            f[2 * j] = v0; f[2 * j + 1] = v1;
            rsum += v0 + v1;
        }
        float4* op = (float4*)(g_xfuse + (size_t)blk * PLANE + row * 56 + cg * 8);
        op[0] = make_float4(f[0], f[1], f[2], f[3]);
        op[1] = make_float4(f[4], f[5], f[6], f[7]);
        partial[tid] = rsum;
    }
    __syncthreads();

    if (tid < 49) {
        const int pr = tid / 7, pc = tid - pr * 7;
        float sm = 0.f;
#pragma unroll
        for (int i = 0; i < 8; i++) sm += partial[(pr * 8 + i) * 7 + pc];
        g_pooled[(b * 49 + tid) * NC + c] = sm * (1.f / 64.f);
    }
}

// ---------------------------------------------------------------------------
// Kernel 2a: hidden layer h = gelu(pw1 @ v + pb1) for all (b, pos).
// grid (5 pos-groups of 10, B). Group 4 row 9 = mean row (pos 49).
// ---------------------------------------------------------------------------
__global__ __launch_bounds__(256) void k_dyn_h(const float* __restrict__ pb1) {
    __shared__ float v[10 * 256];

    const int pg = blockIdx.x, b = blockIdx.y, t = threadIdx.x;
    const int base = pg * 10;
    const int nload = (pg == 4) ? 9 : 10;

    for (int i = t; i < nload * 256; i += 256)
        v[i] = g_pooled[(b * 49 + base) * NC + i];
    if (pg == 4) {
        float sm = 0.f;
        for (int p = 0; p < 49; p++) sm += g_pooled[(b * 49 + p) * NC + t];
        v[9 * 256 + t] = sm * (1.f / 49.f);
    }
    __syncthreads();

    const int o = t & 63;
    for (int pl = t >> 6; pl < 10; pl += 4) {
        const float* vr = &v[pl * 256];
        float acc0 = 0.f, acc1 = 0.f;      // 2-way split: halve serial chain
#pragma unroll 8
        for (int k = 0; k < 256; k += 2) {
            acc0 += g_pw1T[k * 64 + o] * vr[k];
            acc1 += g_pw1T[(k + 1) * 64 + o] * vr[k + 1];
        }
        float x = acc0 + acc1 + pb1[o];
        g_h[(b * 50 + base + pl) * 64 + o] =
            0.5f * x * (1.f + erff(x * 0.70710678118654752f));
    }
}

// ---------------------------------------------------------------------------
// Kernel 2b: logits = h @ pw2 (+pb2), softmax over G, weighted sums.
// grid (8 c-slices of 32, B); each block reads its pw2 slice once.
// ---------------------------------------------------------------------------
__global__ __launch_bounds__(256) void k_dyn2(
    const float* __restrict__ pb2, const float* __restrict__ bias1) {
    __shared__ float hs[50 * 64];

    const int b = blockIdx.y, t = threadIdx.x;
    const int c = blockIdx.x * 32 + (t & 31);
    const int ps = t >> 5;                 // 0..7 pos stripe

    for (int i = t; i < 3200; i += 256) hs[i] = g_h[b * 3200 + i];
    __syncthreads();

    const int np = (ps < 2) ? 7 : 6;       // positions ps, ps+8, ...
    float acc[7][4];
#pragma unroll
    for (int i = 0; i < 7; i++)
#pragma unroll
        for (int g = 0; g < 4; g++) acc[i][g] = 0.f;

    for (int k = 0; k < 64; k++) {
        const float w0 = g_pw2T[k * 1024 + c];
        const float w1 = g_pw2T[k * 1024 + 256 + c];
        const float w2 = g_pw2T[k * 1024 + 512 + c];
        const float w3 = g_pw2T[k * 1024 + 768 + c];
#pragma unroll
        for (int i = 0; i < 7; i++) {
            if (i < np) {
                const float h = hs[(ps + 8 * i) * 64 + k];
                acc[i][0] += h * w0;
                acc[i][1] += h * w1;
                acc[i][2] += h * w2;
                acc[i][3] += h * w3;
            }
        }
    }

    const float q0 = pb2[c], q1 = pb2[256 + c], q2 = pb2[512 + c], q3 = pb2[768 + c];
#pragma unroll
    for (int i = 0; i < 7; i++) {
        if (i >= np) break;
        const int pos = ps + 8 * i;
        float l0 = acc[i][0] + q0, l1 = acc[i][1] + q1;
        float l2 = acc[i][2] + q2, l3 = acc[i][3] + q3;
        float m = fmaxf(fmaxf(l0, l1), fmaxf(l2, l3));
        float e0 = expf(l0 - m), e1 = expf(l1 - m);
        float e2 = expf(l2 - m), e3 = expf(l3 - m);
        float inv = 1.f / (e0 + e1 + e2 + e3);
        if (pos < 49) {
            const float* wp = &g_w1T[pos * 1024];
            float wv = e0 * wp[c] + e1 * wp[256 + c] + e2 * wp[512 + c] +
                       e3 * wp[768 + c];
            g_wdyn[(b * 49 + pos) * NC + c] = wv * inv;
        } else {
            float bv = e0 * bias1[c] + e1 * bias1[256 + c] +
                       e2 * bias1[512 + c] + e3 * bias1[768 + c];
            g_bdyn[b * NC + c] = bv * inv;
        }
    }
}

// ---------------------------------------------------------------------------
// Kernel 3: per-sample dynamic 7x7 depthwise conv + dynamic bias.
// (R4 form: stride 66, LDS.64 row reads, po register-pair recombine.)
// ---------------------------------------------------------------------------
__global__ __launch_bounds__(448, 3) void k_conv(float* __restrict__ out) {
    __shared__ float s[62 * 66];           // tile, halo 3, stride 66
    __shared__ float2 wsm2[49];            // packed (w,w)
    __shared__ float bsm;

    const int blk = blockIdx.x;
    const int b = blk >> 8, c = blk & 255;
    const int tid = threadIdx.x;

    // halo zeroing: 708 cells, looped over 448 threads.
    for (int i = tid; i < 708; i += 448) {
        if (i < 372) {
            int rr = i / 62, x = i - rr * 62;
            int r = (rr < 3) ? rr : 56 + rr;
            s[r * 66 + x] = 0.f;
        } else {
            int j = i - 372;
            int rr = 3 + j / 6, xs = j - (j / 6) * 6;
            int x = (xs < 3) ? xs : 56 + xs;
            s[rr * 66 + x] = 0.f;
        }
    }
    {
        const float4* __restrict__ xp4 =
            (const float4*)(g_xfuse + (size_t)blk * PLANE);
        for (int idx = tid; idx < 784; idx += 448) {
            int r = idx / 14, c4 = idx - r * 14;
            float4 v = xp4[idx];
            float* d = &s[(r + 3) * 66 + 3 + c4 * 4];
            d[0] = v.x; d[1] = v.y; d[2] = v.z; d[3] = v.w;
        }
    }
    if (tid < 49) {
        float w = g_wdyn[(b * 49 + tid) * NC + c];
        wsm2[tid] = make_float2(w, w);
    }
    if (tid == 63) bsm = g_bdyn[b * NC + c];
    __syncthreads();

    if (tid < 392) {
        const int row = tid / 7;
        const int cg = tid - row * 7;
        ull acc[4] = {0, 0, 0, 0};
#pragma unroll
        for (int ky = 0; ky < 7; ky++) {
            const float* rp = &s[(row + ky) * 66 + cg * 8];
            ull pe[7];
#pragma unroll
            for (int k = 0; k < 7; k++) pe[k] = *(const ull*)(rp + 2 * k);
            ull po[6];
#pragma unroll
            for (int m = 0; m < 6; m++)
                po[m] = (pe[m] >> 32) | (pe[m + 1] << 32);
#pragma unroll
            for (int t = 0; t < 4; t++) {   // kx = 0,2,4,6
                ull w = *(const ull*)&wsm2[ky * 7 + 2 * t];
#pragma unroll
                for (int j = 0; j < 4; j++) ffma2(acc[j], w, pe[j + t]);
            }
#pragma unroll
            for (int t = 0; t < 3; t++) {   // kx = 1,3,5
                ull w = *(const ull*)&wsm2[ky * 7 + 2 * t + 1];
#pragma unroll
                for (int j = 0; j < 4; j++) ffma2(acc[j], w, po[j + t]);
            }
        }
        const float bv = bsm;
        float2 p0 = u2f2(acc[0]), p1 = u2f2(acc[1]);
        float2 p2 = u2f2(acc[2]), p3 = u2f2(acc[3]);
        float4* op = (float4*)(out + (size_t)blk * PLANE + row * 56 + cg * 8);
        op[0] = make_float4(p0.x + bv, p0.y + bv, p1.x + bv, p1.y + bv);
        op[1] = make_float4(p2.x + bv, p2.y + bv, p3.x + bv, p3.y + bv);
    }
}

// ---------------------------------------------------------------------------
extern "C" void kernel_launch(void* const* d_in, const int* in_sizes, int n_in,
                              void* d_out, int out_size) {
    const float* x1    = (const float*)d_in[0];
    const float* dw1_w = (const float*)d_in[1];
    const float* dw1_g = (const float*)d_in[2];
    const float* dw1_b = (const float*)d_in[3];
    const float* dw1_m = (const float*)d_in[4];
    const float* dw1_v = (const float*)d_in[5];
    const float* dw2_w = (const float*)d_in[6];
    const float* dw2_g = (const float*)d_in[7];
    const float* dw2_b = (const float*)d_in[8];
    const float* dw2_m = (const float*)d_in[9];
    const float* dw2_v = (const float*)d_in[10];
    const float* weight1 = (const float*)d_in[11];
    const float* bias1   = (const float*)d_in[12];
    const float* pw1 = (const float*)d_in[13];
    const float* pb1 = (const float*)d_in[14];
    const float* pw2 = (const float*)d_in[15];
    const float* pb2 = (const float*)d_in[16];
    float* out = (float*)d_out;

    k_fuse<<<NPLANES + 295, 448>>>(x1, dw1_w, dw1_g, dw1_b, dw1_m, dw1_v,
                                   dw2_w, dw2_g, dw2_b, dw2_m, dw2_v,
                                   pw1, pw2, weight1);
    k_dyn_h<<<dim3(5, NB), 256>>>(pb1);
    k_dyn2<<<dim3(8, NB), 256>>>(pb2, bias1);
    k_conv<<<NPLANES, 448>>>(out);
}

// round 8
// speedup vs baseline: 1.1242x; 1.1242x over previous
#include <cuda_runtime.h>
#include <math.h>

#define NB 16
#define NC 256
#define PLANE 3136
#define NPLANES 4096
typedef unsigned long long ull;

// scratch (static device globals; no allocation)
__device__ float g_xfuse[NPLANES * PLANE];   // 51.4 MB
__device__ float g_pooled[NB * 49 * NC];     // [B][pos][C]
__device__ float g_h[NB * 50 * 64];          // hidden layer (pos 49 = mean)
__device__ float g_wdyn[NB * 49 * NC];       // [B][pos][C]
__device__ float g_bdyn[NB * NC];            // [B][C]
__device__ float g_pw1T[256 * 64];           // [k][o]
__device__ float g_pw2T[64 * 1024];          // [k][oc]
__device__ float g_w1T[49 * 1024];           // [pos][g*C+c]

__device__ __forceinline__ void ffma2(ull& d, ull a, ull b) {
    asm("fma.rn.f32x2 %0, %1, %2, %0;" : "+l"(d) : "l"(a), "l"(b));
}
__device__ __forceinline__ float2 u2f2(ull v) {
    float2 r;
    r.x = __uint_as_float((unsigned)v);
    r.y = __uint_as_float((unsigned)(v >> 32));
    return r;
}

// ---------------------------------------------------------------------------
// Kernel 1: fused dw3x3+BN (x2), relu6 gate, x_fuse, 7x7 block-mean pool.
// Blocks >= NPLANES instead perform the small weight transposes.
// (Frozen R4 form.)
// ---------------------------------------------------------------------------
__global__ __launch_bounds__(448, 3) void k_fuse(
    const float* __restrict__ x1,
    const float* __restrict__ dw1_w, const float* __restrict__ dw1_g,
    const float* __restrict__ dw1_b, const float* __restrict__ dw1_m,
    const float* __restrict__ dw1_v,
    const float* __restrict__ dw2_w, const float* __restrict__ dw2_g,
    const float* __restrict__ dw2_b, const float* __restrict__ dw2_m,
    const float* __restrict__ dw2_v,
    const float* __restrict__ pw1, const float* __restrict__ pw2,
    const float* __restrict__ w1grp) {
    const int tid = threadIdx.x;

    if (blockIdx.x >= NPLANES) {           // transpose side-work
        int i = (blockIdx.x - NPLANES) * 448 + tid;
        if (i < 16384) {                   // pw1 [64,256] -> [256,64]
            int k = i >> 6, o = i & 63;
            g_pw1T[i] = pw1[o * 256 + k];
        } else if (i < 81920) {            // pw2 [1024,64] -> [64,1024]
            int j = i - 16384;
            int k = j >> 10, oc = j & 1023;
            g_pw2T[j] = pw2[oc * 64 + k];
        } else if (i < 132096) {           // weight1 [G*C,49] -> [49,G*C]
            int l = i - 81920;
            int pos = l / 1024, gc = l & 1023;
            g_w1T[l] = w1grp[gc * 49 + pos];
        }
        return;
    }

    __shared__ float s[58 * 60];           // tile, halo 1, stride 60
    __shared__ float2 sw1[9], sw2[9];      // packed (w,w) weights
    __shared__ float partial[392];

    const int blk = blockIdx.x;
    const int b = blk >> 8, c = blk & 255;

    // halo zeroing (rows 0,57 x 0..57; rows 1..56 x in {0,57}); interior f4
    if (tid < 228) {
        if (tid < 116) {
            int r = (tid < 58) ? 0 : 57;
            int x = (tid < 58) ? tid : tid - 58;
            s[r * 60 + x] = 0.f;
        } else {
            int j = tid - 116;
            int r = 1 + (j >> 1);
            int x = (j & 1) ? 57 : 0;
            s[r * 60 + x] = 0.f;
        }
    }
    {
        const float4* __restrict__ xp4 =
            (const float4*)(x1 + (size_t)blk * PLANE);
        for (int idx = tid; idx < 784; idx += 448) {
            int r = idx / 14, c4 = idx - r * 14;
            float4 v = xp4[idx];
            float* d = &s[(r + 1) * 60 + 1 + c4 * 4];
            d[0] = v.x; d[1] = v.y; d[2] = v.z; d[3] = v.w;
        }
    }
    // BN-folded channel scalars
    const float s1 = dw1_g[c] * rsqrtf(dw1_v[c] + 1e-5f);
    const float s2 = dw2_g[c] * rsqrtf(dw2_v[c] + 1e-5f);
    const float bb1 = dw1_b[c] - dw1_m[c] * s1;
    const float bb2 = dw2_b[c] - dw2_m[c] * s2;
    if (tid < 9) {
        float wa = dw1_w[c * 9 + tid] * s1;
        float wb = dw2_w[c * 9 + tid] * s2;
        sw1[tid] = make_float2(wa, wa);
        sw2[tid] = make_float2(wb, wb);
    }
    __syncthreads();

    if (tid < 392) {
        const int row = tid / 7;
        const int cg = tid - row * 7;
        ull aA[4] = {0, 0, 0, 0}, aB[4] = {0, 0, 0, 0};
#pragma unroll
        for (int ky = 0; ky < 3; ky++) {
            const float* rp = &s[(row + ky) * 60 + cg * 8];
            ull pe[5];
#pragma unroll
            for (int k = 0; k < 5; k++) pe[k] = *(const ull*)(rp + 2 * k);
            ull po[4];
#pragma unroll
            for (int m = 0; m < 4; m++)
                po[m] = (pe[m] >> 32) | (pe[m + 1] << 32);
#pragma unroll
            for (int t = 0; t < 2; t++) {   // kx = 0, 2
                ull wa = *(const ull*)&sw1[ky * 3 + 2 * t];
                ull wb = *(const ull*)&sw2[ky * 3 + 2 * t];
#pragma unroll
                for (int j = 0; j < 4; j++) {
                    ffma2(aA[j], wa, pe[j + t]);
                    ffma2(aB[j], wb, pe[j + t]);
                }
            }
            {                               // kx = 1
                ull wa = *(const ull*)&sw1[ky * 3 + 1];
                ull wb = *(const ull*)&sw2[ky * 3 + 1];
#pragma unroll
                for (int j = 0; j < 4; j++) {
                    ffma2(aA[j], wa, po[j]);
                    ffma2(aB[j], wb, po[j]);
                }
            }
        }
        float f[8];
        float rsum = 0.f;
#pragma unroll
        for (int j = 0; j < 4; j++) {
            float2 pa = u2f2(aA[j]), pb = u2f2(aB[j]);
            float a0 = fminf(fmaxf(pa.x + bb1, 0.f), 6.f);
            float a1 = fminf(fmaxf(pa.y + bb1, 0.f), 6.f);
            float v0 = a0 * (pb.x + bb2);
            float v1 = a1 * (pb.y + bb2);
            f[2 * j] = v0; f[2 * j + 1] = v1;
            rsum += v0 + v1;
        }
        float4* op = (float4*)(g_xfuse + (size_t)blk * PLANE + row * 56 + cg * 8);
        op[0] = make_float4(f[0], f[1], f[2], f[3]);
        op[1] = make_float4(f[4], f[5], f[6], f[7]);
        partial[tid] = rsum;
    }
    __syncthreads();

    if (tid < 49) {
        const int pr = tid / 7, pc = tid - pr * 7;
        float sm = 0.f;
#pragma unroll
        for (int i = 0; i < 8; i++) sm += partial[(pr * 8 + i) * 7 + pc];
        g_pooled[(b * 49 + tid) * NC + c] = sm * (1.f / 64.f);
    }
}

// ---------------------------------------------------------------------------
// Kernel 2a: hidden layer h = gelu(pw1 @ v + pb1) for all (b, pos).
// ---------------------------------------------------------------------------
__global__ __launch_bounds__(256) void k_dyn_h(const float* __restrict__ pb1) {
    __shared__ float v[10 * 256];

    const int pg = blockIdx.x, b = blockIdx.y, t = threadIdx.x;
    const int base = pg * 10;
    const int nload = (pg == 4) ? 9 : 10;

    for (int i = t; i < nload * 256; i += 256)
        v[i] = g_pooled[(b * 49 + base) * NC + i];
    if (pg == 4) {
        float sm = 0.f;
        for (int p = 0; p < 49; p++) sm += g_pooled[(b * 49 + p) * NC + t];
        v[9 * 256 + t] = sm * (1.f / 49.f);
    }
    __syncthreads();

    const int o = t & 63;
    for (int pl = t >> 6; pl < 10; pl += 4) {
        const float* vr = &v[pl * 256];
        float acc0 = 0.f, acc1 = 0.f;
#pragma unroll 8
        for (int k = 0; k < 256; k += 2) {
            acc0 += g_pw1T[k * 64 + o] * vr[k];
            acc1 += g_pw1T[(k + 1) * 64 + o] * vr[k + 1];
        }
        float x = acc0 + acc1 + pb1[o];
        g_h[(b * 50 + base + pl) * 64 + o] =
            0.5f * x * (1.f + erff(x * 0.70710678118654752f));
    }
}

// ---------------------------------------------------------------------------
// Kernel 2b: logits = h @ pw2 (+pb2), softmax over G, weighted sums.
// ---------------------------------------------------------------------------
__global__ __launch_bounds__(256) void k_dyn2(
    const float* __restrict__ pb2, const float* __restrict__ bias1) {
    __shared__ float hs[50 * 64];

    const int b = blockIdx.y, t = threadIdx.x;
    const int c = blockIdx.x * 32 + (t & 31);
    const int ps = t >> 5;                 // 0..7 pos stripe

    for (int i = t; i < 3200; i += 256) hs[i] = g_h[b * 3200 + i];
    __syncthreads();

    const int np = (ps < 2) ? 7 : 6;       // positions ps, ps+8, ...
    float acc[7][4];
#pragma unroll
    for (int i = 0; i < 7; i++)
#pragma unroll
        for (int g = 0; g < 4; g++) acc[i][g] = 0.f;

#pragma unroll 4
    for (int k = 0; k < 64; k++) {
        const float w0 = g_pw2T[k * 1024 + c];
        const float w1 = g_pw2T[k * 1024 + 256 + c];
        const float w2 = g_pw2T[k * 1024 + 512 + c];
        const float w3 = g_pw2T[k * 1024 + 768 + c];
#pragma unroll
        for (int i = 0; i < 7; i++) {
            if (i < np) {
                const float h = hs[(ps + 8 * i) * 64 + k];
                acc[i][0] += h * w0;
                acc[i][1] += h * w1;
                acc[i][2] += h * w2;
                acc[i][3] += h * w3;
            }
        }
    }

    const float q0 = pb2[c], q1 = pb2[256 + c], q2 = pb2[512 + c], q3 = pb2[768 + c];
#pragma unroll
    for (int i = 0; i < 7; i++) {
        if (i >= np) break;
        const int pos = ps + 8 * i;
        float l0 = acc[i][0] + q0, l1 = acc[i][1] + q1;
        float l2 = acc[i][2] + q2, l3 = acc[i][3] + q3;
        float m = fmaxf(fmaxf(l0, l1), fmaxf(l2, l3));
        float e0 = expf(l0 - m), e1 = expf(l1 - m);
        float e2 = expf(l2 - m), e3 = expf(l3 - m);
        float inv = 1.f / (e0 + e1 + e2 + e3);
        if (pos < 49) {
            const float* wp = &g_w1T[pos * 1024];
            float wv = e0 * wp[c] + e1 * wp[256 + c] + e2 * wp[512 + c] +
                       e3 * wp[768 + c];
            g_wdyn[(b * 49 + pos) * NC + c] = wv * inv;
        } else {
            float bv = e0 * bias1[c] + e1 * bias1[256 + c] +
                       e2 * bias1[512 + c] + e3 * bias1[768 + c];
            g_bdyn[b * NC + c] = bv * inv;
        }
    }
}

// ---------------------------------------------------------------------------
// Kernel 3: dynamic 7x7 depthwise conv, 2-row register blocking.
// Block = 224 threads = 7 warps; warp w owns column-group cg=w, lane owns
// row-pair pr (pr<28). Bank = (2*pr + const) mod 32 -> conflict-free LDS.64.
// Each input row is loaded once and feeds both output rows; weights carried
// in registers across the ri loop (row ri serves ky=ri and ky=ri-1).
// ---------------------------------------------------------------------------
__global__ __launch_bounds__(224, 4) void k_conv(float* __restrict__ out) {
    __shared__ float s[62 * 66];           // tile, halo 3, stride 66
    __shared__ float2 wsm2[49];            // packed (w,w)
    __shared__ float bsm;

    const int blk = blockIdx.x;
    const int b = blk >> 8, c = blk & 255;
    const int tid = threadIdx.x;

    // halo zeroing: 708 cells, looped over 224 threads.
    for (int i = tid; i < 708; i += 224) {
        if (i < 372) {
            int rr = i / 62, x = i - rr * 62;
            int r = (rr < 3) ? rr : 56 + rr;
            s[r * 66 + x] = 0.f;
        } else {
            int j = i - 372;
            int rr = 3 + j / 6, xs = j - (j / 6) * 6;
            int x = (xs < 3) ? xs : 56 + xs;
            s[rr * 66 + x] = 0.f;
        }
    }
    {
        const float4* __restrict__ xp4 =
            (const float4*)(g_xfuse + (size_t)blk * PLANE);
        for (int idx = tid; idx < 784; idx += 224) {
            int r = idx / 14, c4 = idx - r * 14;
            float4 v = xp4[idx];
            float* d = &s[(r + 3) * 66 + 3 + c4 * 4];
            d[0] = v.x; d[1] = v.y; d[2] = v.z; d[3] = v.w;
        }
    }
    if (tid < 49) {
        float w = g_wdyn[(b * 49 + tid) * NC + c];
        wsm2[tid] = make_float2(w, w);
    }
    if (tid == 63) bsm = g_bdyn[b * NC + c];
    __syncthreads();

    const int pr = tid & 31;               // row pair (lane)
    const int cg = tid >> 5;               // column group (warp id)
    if (pr < 28) {
        const int r0 = 2 * pr;             // output rows r0, r0+1
        ull acc0[4] = {0, 0, 0, 0};        // out row r0
        ull acc1[4] = {0, 0, 0, 0};        // out row r0+1
        ull wrow[7];                       // weights of previous input row
#pragma unroll
        for (int ri = 0; ri < 8; ri++) {   // input rows r0..r0+7 (padded idx)
            const float* rp = &s[(r0 + ri) * 66 + cg * 8];
            ull pe[7];
#pragma unroll
            for (int k = 0; k < 7; k++) pe[k] = *(const ull*)(rp + 2 * k);
            ull po[6];
#pragma unroll
            for (int m = 0; m < 6; m++)
                po[m] = (pe[m] >> 32) | (pe[m + 1] << 32);

            ull wnew[7];
            if (ri < 7) {                  // load weights for ky = ri
#pragma unroll
                for (int kx = 0; kx < 7; kx++)
                    wnew[kx] = *(const ull*)&wsm2[ri * 7 + kx];
                // out row r0: tap ky = ri
#pragma unroll
                for (int t = 0; t < 4; t++)     // kx = 0,2,4,6
#pragma unroll
                    for (int j = 0; j < 4; j++) ffma2(acc0[j], wnew[2 * t], pe[j + t]);
#pragma unroll
                for (int t = 0; t < 3; t++)     // kx = 1,3,5
#pragma unroll
                    for (int j = 0; j < 4; j++) ffma2(acc0[j], wnew[2 * t + 1], po[j + t]);
            }
            if (ri >= 1) {                 // out row r0+1: tap ky = ri-1
#pragma unroll
                for (int t = 0; t < 4; t++)
#pragma unroll
                    for (int j = 0; j < 4; j++) ffma2(acc1[j], wrow[2 * t], pe[j + t]);
#pragma unroll
                for (int t = 0; t < 3; t++)
#pragma unroll
                    for (int j = 0; j < 4; j++) ffma2(acc1[j], wrow[2 * t + 1], po[j + t]);
            }
            if (ri < 7) {
#pragma unroll
                for (int kx = 0; kx < 7; kx++) wrow[kx] = wnew[kx];
            }
        }
        const float bv = bsm;
        {
            float2 p0 = u2f2(acc0[0]), p1 = u2f2(acc0[1]);
            float2 p2 = u2f2(acc0[2]), p3 = u2f2(acc0[3]);
            float4* op = (float4*)(out + (size_t)blk * PLANE + r0 * 56 + cg * 8);
            op[0] = make_float4(p0.x + bv, p0.y + bv, p1.x + bv, p1.y + bv);
            op[1] = make_float4(p2.x + bv, p2.y + bv, p3.x + bv, p3.y + bv);
        }
        {
            float2 p0 = u2f2(acc1[0]), p1 = u2f2(acc1[1]);
            float2 p2 = u2f2(acc1[2]), p3 = u2f2(acc1[3]);
            float4* op = (float4*)(out + (size_t)blk * PLANE + (r0 + 1) * 56 + cg * 8);
            op[0] = make_float4(p0.x + bv, p0.y + bv, p1.x + bv, p1.y + bv);
            op[1] = make_float4(p2.x + bv, p2.y + bv, p3.x + bv, p3.y + bv);
        }
    }
}

// ---------------------------------------------------------------------------
extern "C" void kernel_launch(void* const* d_in, const int* in_sizes, int n_in,
                              void* d_out, int out_size) {
    const float* x1    = (const float*)d_in[0];
    const float* dw1_w = (const float*)d_in[1];
    const float* dw1_g = (const float*)d_in[2];
    const float* dw1_b = (const float*)d_in[3];
    const float* dw1_m = (const float*)d_in[4];
    const float* dw1_v = (const float*)d_in[5];
    const float* dw2_w = (const float*)d_in[6];
    const float* dw2_g = (const float*)d_in[7];
    const float* dw2_b = (const float*)d_in[8];
    const float* dw2_m = (const float*)d_in[9];
    const float* dw2_v = (const float*)d_in[10];
    const float* weight1 = (const float*)d_in[11];
    const float* bias1   = (const float*)d_in[12];
    const float* pw1 = (const float*)d_in[13];
    const float* pb1 = (const float*)d_in[14];
    const float* pw2 = (const float*)d_in[15];
    const float* pb2 = (const float*)d_in[16];
    float* out = (float*)d_out;

    k_fuse<<<NPLANES + 295, 448>>>(x1, dw1_w, dw1_g, dw1_b, dw1_m, dw1_v,
                                   dw2_w, dw2_g, dw2_b, dw2_m, dw2_v,
                                   pw1, pw2, weight1);
    k_dyn_h<<<dim3(5, NB), 256>>>(pb1);
    k_dyn2<<<dim3(8, NB), 256>>>(pb2, bias1);
    k_conv<<<NPLANES, 224>>>(out);
}

// round 9
// speedup vs baseline: 1.1826x; 1.0520x over previous
#include <cuda_runtime.h>
#include <math.h>

#define NB 16
#define NC 256
#define PLANE 3136
#define NPLANES 4096
typedef unsigned long long ull;

// scratch (static device globals; no allocation)
__device__ float g_xfuse[NPLANES * PLANE];   // 51.4 MB
__device__ float g_pooled[NB * 49 * NC];     // [B][pos][C]
__device__ float g_h[NB * 50 * 64];          // hidden layer (pos 49 = mean)
__device__ float g_wdyn[NB * 49 * NC];       // [B][pos][C]
__device__ float g_bdyn[NB * NC];            // [B][C]
__device__ float g_pw1T[256 * 64];           // [k][o]
__device__ float g_pw2T[64 * 1024];          // [k][oc]
__device__ float g_w1T[49 * 1024];           // [pos][g*C+c]

__device__ __forceinline__ void ffma2(ull& d, ull a, ull b) {
    asm("fma.rn.f32x2 %0, %1, %2, %0;" : "+l"(d) : "l"(a), "l"(b));
}
__device__ __forceinline__ float2 u2f2(ull v) {
    float2 r;
    r.x = __uint_as_float((unsigned)v);
    r.y = __uint_as_float((unsigned)(v >> 32));
    return r;
}

// ---------------------------------------------------------------------------
// Kernel 1: fused dw3x3+BN (x2), relu6 gate, x_fuse, 7x7 block-mean pool.
// Mapping: warp = column-group, lane = row  ->  conflict-free LDS.64
// (bank = (2*lane + const) mod 32, distinct per 16-lane phase).
// Blocks >= NPLANES instead perform the small weight transposes.
// ---------------------------------------------------------------------------
__global__ __launch_bounds__(448, 3) void k_fuse(
    const float* __restrict__ x1,
    const float* __restrict__ dw1_w, const float* __restrict__ dw1_g,
    const float* __restrict__ dw1_b, const float* __restrict__ dw1_m,
    const float* __restrict__ dw1_v,
    const float* __restrict__ dw2_w, const float* __restrict__ dw2_g,
    const float* __restrict__ dw2_b, const float* __restrict__ dw2_m,
    const float* __restrict__ dw2_v,
    const float* __restrict__ pw1, const float* __restrict__ pw2,
    const float* __restrict__ w1grp) {
    const int tid = threadIdx.x;

    if (blockIdx.x >= NPLANES) {           // transpose side-work
        int i = (blockIdx.x - NPLANES) * 448 + tid;
        if (i < 16384) {                   // pw1 [64,256] -> [256,64]
            int k = i >> 6, o = i & 63;
            g_pw1T[i] = pw1[o * 256 + k];
        } else if (i < 81920) {            // pw2 [1024,64] -> [64,1024]
            int j = i - 16384;
            int k = j >> 10, oc = j & 1023;
            g_pw2T[j] = pw2[oc * 64 + k];
        } else if (i < 132096) {           // weight1 [G*C,49] -> [49,G*C]
            int l = i - 81920;
            int pos = l / 1024, gc = l & 1023;
            g_w1T[l] = w1grp[gc * 49 + pos];
        }
        return;
    }

    __shared__ float s[58 * 66];           // tile, halo 1, stride 66
    __shared__ float2 sw1[9], sw2[9];      // packed (w,w) weights
    __shared__ float partial[392];

    const int blk = blockIdx.x;
    const int b = blk >> 8, c = blk & 255;

    // halo zeroing (rows 0,57 x 0..57; rows 1..56 x in {0,57}): 228 cells
    if (tid < 228) {
        int r, x;
        if (tid < 116) {
            r = (tid < 58) ? 0 : 57;
            x = (tid < 58) ? tid : tid - 58;
        } else {
            int j = tid - 116;
            r = 1 + (j >> 1);
            x = (j & 1) ? 57 : 0;
        }
        s[r * 66 + x] = 0.f;
    }
    {
        const float4* __restrict__ xp4 =
            (const float4*)(x1 + (size_t)blk * PLANE);
        for (int idx = tid; idx < 784; idx += 448) {
            int r = idx / 14, c4 = idx - r * 14;
            float4 v = xp4[idx];
            float* d = &s[(r + 1) * 66 + 1 + c4 * 4];
            d[0] = v.x; d[1] = v.y; d[2] = v.z; d[3] = v.w;
        }
    }
    // BN-folded channel scalars
    const float s1 = dw1_g[c] * rsqrtf(dw1_v[c] + 1e-5f);
    const float s2 = dw2_g[c] * rsqrtf(dw2_v[c] + 1e-5f);
    const float bb1 = dw1_b[c] - dw1_m[c] * s1;
    const float bb2 = dw2_b[c] - dw2_m[c] * s2;
    if (tid < 9) {
        float wa = dw1_w[c * 9 + tid] * s1;
        float wb = dw2_w[c * 9 + tid] * s2;
        sw1[tid] = make_float2(wa, wa);
        sw2[tid] = make_float2(wb, wb);
    }
    __syncthreads();

    const int wp = tid >> 5, lane = tid & 31;
    const int band = (wp >= 7) ? 1 : 0;
    const int cg = wp - band * 7;
    const int row = band * 32 + lane;

    if (row < 56) {
        ull aA[4] = {0, 0, 0, 0}, aB[4] = {0, 0, 0, 0};
#pragma unroll
        for (int ky = 0; ky < 3; ky++) {
            const float* rp = &s[(row + ky) * 66 + cg * 8];
            ull pe[5];
#pragma unroll
            for (int k = 0; k < 5; k++) pe[k] = *(const ull*)(rp + 2 * k);
            ull po[4];
#pragma unroll
            for (int m = 0; m < 4; m++)
                po[m] = (pe[m] >> 32) | (pe[m + 1] << 32);
#pragma unroll
            for (int t = 0; t < 2; t++) {   // kx = 0, 2
                ull wa = *(const ull*)&sw1[ky * 3 + 2 * t];
                ull wb = *(const ull*)&sw2[ky * 3 + 2 * t];
#pragma unroll
                for (int j = 0; j < 4; j++) {
                    ffma2(aA[j], wa, pe[j + t]);
                    ffma2(aB[j], wb, pe[j + t]);
                }
            }
            {                               // kx = 1
                ull wa = *(const ull*)&sw1[ky * 3 + 1];
                ull wb = *(const ull*)&sw2[ky * 3 + 1];
#pragma unroll
                for (int j = 0; j < 4; j++) {
                    ffma2(aA[j], wa, po[j]);
                    ffma2(aB[j], wb, po[j]);
                }
            }
        }
        float f[8];
        float rsum = 0.f;
#pragma unroll
        for (int j = 0; j < 4; j++) {
            float2 pa = u2f2(aA[j]), pb = u2f2(aB[j]);
            float a0 = fminf(fmaxf(pa.x + bb1, 0.f), 6.f);
            float a1 = fminf(fmaxf(pa.y + bb1, 0.f), 6.f);
            float v0 = a0 * (pb.x + bb2);
            float v1 = a1 * (pb.y + bb2);
            f[2 * j] = v0; f[2 * j + 1] = v1;
            rsum += v0 + v1;
        }
        float4* op = (float4*)(g_xfuse + (size_t)blk * PLANE + row * 56 + cg * 8);
        op[0] = make_float4(f[0], f[1], f[2], f[3]);
        op[1] = make_float4(f[4], f[5], f[6], f[7]);
        partial[row * 7 + cg] = rsum;      // same layout as before
    }
    __syncthreads();

    if (tid < 49) {
        const int pr = tid / 7, pc = tid - pr * 7;
        float sm = 0.f;
#pragma unroll
        for (int i = 0; i < 8; i++) sm += partial[(pr * 8 + i) * 7 + pc];
        g_pooled[(b * 49 + tid) * NC + c] = sm * (1.f / 64.f);
    }
}

// ---------------------------------------------------------------------------
// Kernel 2a: hidden layer h = gelu(pw1 @ v + pb1) for all (b, pos).
// ---------------------------------------------------------------------------
__global__ __launch_bounds__(256) void k_dyn_h(const float* __restrict__ pb1) {
    __shared__ float v[10 * 256];

    const int pg = blockIdx.x, b = blockIdx.y, t = threadIdx.x;
    const int base = pg * 10;
    const int nload = (pg == 4) ? 9 : 10;

    for (int i = t; i < nload * 256; i += 256)
        v[i] = g_pooled[(b * 49 + base) * NC + i];
    if (pg == 4) {
        float sm = 0.f;
        for (int p = 0; p < 49; p++) sm += g_pooled[(b * 49 + p) * NC + t];
        v[9 * 256 + t] = sm * (1.f / 49.f);
    }
    __syncthreads();

    const int o = t & 63;
    for (int pl = t >> 6; pl < 10; pl += 4) {
        const float* vr = &v[pl * 256];
        float acc0 = 0.f, acc1 = 0.f;
#pragma unroll 8
        for (int k = 0; k < 256; k += 2) {
            acc0 += g_pw1T[k * 64 + o] * vr[k];
            acc1 += g_pw1T[(k + 1) * 64 + o] * vr[k + 1];
        }
        float x = acc0 + acc1 + pb1[o];
        g_h[(b * 50 + base + pl) * 64 + o] =
            0.5f * x * (1.f + erff(x * 0.70710678118654752f));
    }
}

// ---------------------------------------------------------------------------
// Kernel 2b: logits = h @ pw2 (+pb2), softmax over G, weighted sums.
// ---------------------------------------------------------------------------
__global__ __launch_bounds__(256) void k_dyn2(
    const float* __restrict__ pb2, const float* __restrict__ bias1) {
    __shared__ float hs[50 * 64];

    const int b = blockIdx.y, t = threadIdx.x;
    const int c = blockIdx.x * 32 + (t & 31);
    const int ps = t >> 5;                 // 0..7 pos stripe

    for (int i = t; i < 3200; i += 256) hs[i] = g_h[b * 3200 + i];
    __syncthreads();

    const int np = (ps < 2) ? 7 : 6;       // positions ps, ps+8, ...
    float acc[7][4];
#pragma unroll
    for (int i = 0; i < 7; i++)
#pragma unroll
        for (int g = 0; g < 4; g++) acc[i][g] = 0.f;

#pragma unroll 4
    for (int k = 0; k < 64; k++) {
        const float w0 = g_pw2T[k * 1024 + c];
        const float w1 = g_pw2T[k * 1024 + 256 + c];
        const float w2 = g_pw2T[k * 1024 + 512 + c];
        const float w3 = g_pw2T[k * 1024 + 768 + c];
#pragma unroll
        for (int i = 0; i < 7; i++) {
            if (i < np) {
                const float h = hs[(ps + 8 * i) * 64 + k];
                acc[i][0] += h * w0;
                acc[i][1] += h * w1;
                acc[i][2] += h * w2;
                acc[i][3] += h * w3;
            }
        }
    }

    const float q0 = pb2[c], q1 = pb2[256 + c], q2 = pb2[512 + c], q3 = pb2[768 + c];
#pragma unroll
    for (int i = 0; i < 7; i++) {
        if (i >= np) break;
        const int pos = ps + 8 * i;
        float l0 = acc[i][0] + q0, l1 = acc[i][1] + q1;
        float l2 = acc[i][2] + q2, l3 = acc[i][3] + q3;
        float m = fmaxf(fmaxf(l0, l1), fmaxf(l2, l3));
        float e0 = expf(l0 - m), e1 = expf(l1 - m);
        float e2 = expf(l2 - m), e3 = expf(l3 - m);
        float inv = 1.f / (e0 + e1 + e2 + e3);
        if (pos < 49) {
            const float* wp = &g_w1T[pos * 1024];
            float wv = e0 * wp[c] + e1 * wp[256 + c] + e2 * wp[512 + c] +
                       e3 * wp[768 + c];
            g_wdyn[(b * 49 + pos) * NC + c] = wv * inv;
        } else {
            float bv = e0 * bias1[c] + e1 * bias1[256 + c] +
                       e2 * bias1[512 + c] + e3 * bias1[768 + c];
            g_bdyn[b * NC + c] = bv * inv;
        }
    }
}

// ---------------------------------------------------------------------------
// Kernel 3: dynamic 7x7 depthwise conv + dynamic bias.
// warp = column-group, lane = row -> conflict-free LDS.64; shifted
// S-accumulators for odd taps (zero recombine MOVs; algebra proven in R5).
// ---------------------------------------------------------------------------
__global__ __launch_bounds__(448, 3) void k_conv(float* __restrict__ out) {
    __shared__ float s[62 * 66];           // tile, halo 3, stride 66
    __shared__ float2 wsm2[49];            // packed (w,w)
    __shared__ float bsm;

    const int blk = blockIdx.x;
    const int b = blk >> 8, c = blk & 255;
    const int tid = threadIdx.x;

    // halo zeroing: 708 cells over 448 threads
    for (int i = tid; i < 708; i += 448) {
        int r, x;
        if (i < 372) {
            int rr = i / 62; x = i - rr * 62;
            r = (rr < 3) ? rr : 56 + rr;
        } else {
            int j = i - 372;
            r = 3 + j / 6;
            int xs = j - (j / 6) * 6;
            x = (xs < 3) ? xs : 56 + xs;
        }
        s[r * 66 + x] = 0.f;
    }
    {
        const float4* __restrict__ xp4 =
            (const float4*)(g_xfuse + (size_t)blk * PLANE);
        for (int idx = tid; idx < 784; idx += 448) {
            int r = idx / 14, c4 = idx - r * 14;
            float4 v = xp4[idx];
            float* d = &s[(r + 3) * 66 + 3 + c4 * 4];
            d[0] = v.x; d[1] = v.y; d[2] = v.z; d[3] = v.w;
        }
    }
    if (tid < 49) {
        float w = g_wdyn[(b * 49 + tid) * NC + c];
        wsm2[tid] = make_float2(w, w);
    }
    if (tid == 63) bsm = g_bdyn[b * NC + c];
    __syncthreads();

    const int wp = tid >> 5, lane = tid & 31;
    const int band = (wp >= 7) ? 1 : 0;
    const int cg = wp - band * 7;
    const int row = band * 32 + lane;

    if (row < 56) {
        ull acc[4] = {0, 0, 0, 0};
        ull S[5] = {0, 0, 0, 0, 0};
#pragma unroll
        for (int ky = 0; ky < 7; ky++) {
            const float* rp = &s[(row + ky) * 66 + cg * 8];
            ull pe[7];
#pragma unroll
            for (int k = 0; k < 7; k++) pe[k] = *(const ull*)(rp + 2 * k);
#pragma unroll
            for (int t = 0; t < 4; t++) {   // even taps kx = 0,2,4,6
                ull w = *(const ull*)&wsm2[ky * 7 + 2 * t];
#pragma unroll
                for (int j = 0; j < 4; j++) ffma2(acc[j], w, pe[j + t]);
            }
#pragma unroll
            for (int t = 0; t < 3; t++) {   // odd taps kx = 1,3,5 -> S[i]
                ull w = *(const ull*)&wsm2[ky * 7 + 2 * t + 1];
#pragma unroll
                for (int i = 0; i < 5; i++) ffma2(S[i], w, pe[i + t]);
            }
        }
        const float bv = bsm;
        float2 a0 = u2f2(acc[0]), a1 = u2f2(acc[1]);
        float2 a2 = u2f2(acc[2]), a3 = u2f2(acc[3]);
        float2 s0 = u2f2(S[0]), s1 = u2f2(S[1]), s2 = u2f2(S[2]);
        float2 s3 = u2f2(S[3]), s4 = u2f2(S[4]);
        float4* op = (float4*)(out + (size_t)blk * PLANE + row * 56 + cg * 8);
        op[0] = make_float4(a0.x + s0.y + bv, a0.y + s1.x + bv,
                            a1.x + s1.y + bv, a1.y + s2.x + bv);
        op[1] = make_float4(a2.x + s2.y + bv, a2.y + s3.x + bv,
                            a3.x + s3.y + bv, a3.y + s4.x + bv);
    }
}

// ---------------------------------------------------------------------------
extern "C" void kernel_launch(void* const* d_in, const int* in_sizes, int n_in,
                              void* d_out, int out_size) {
    const float* x1    = (const float*)d_in[0];
    const float* dw1_w = (const float*)d_in[1];
    const float* dw1_g = (const float*)d_in[2];
    const float* dw1_b = (const float*)d_in[3];
    const float* dw1_m = (const float*)d_in[4];
    const float* dw1_v = (const float*)d_in[5];
    const float* dw2_w = (const float*)d_in[6];
    const float* dw2_g = (const float*)d_in[7];
    const float* dw2_b = (const float*)d_in[8];
    const float* dw2_m = (const float*)d_in[9];
    const float* dw2_v = (const float*)d_in[10];
    const float* weight1 = (const float*)d_in[11];
    const float* bias1   = (const float*)d_in[12];
    const float* pw1 = (const float*)d_in[13];
    const float* pb1 = (const float*)d_in[14];
    const float* pw2 = (const float*)d_in[15];
    const float* pb2 = (const float*)d_in[16];
    float* out = (float*)d_out;

    k_fuse<<<NPLANES + 295, 448>>>(x1, dw1_w, dw1_g, dw1_b, dw1_m, dw1_v,
                                   dw2_w, dw2_g, dw2_b, dw2_m, dw2_v,
                                   pw1, pw2, weight1);
    k_dyn_h<<<dim3(5, NB), 256>>>(pb1);
    k_dyn2<<<dim3(8, NB), 256>>>(pb2, bias1);
    k_conv<<<NPLANES, 448>>>(out);
}